// round 6
// baseline (speedup 1.0000x reference)
#include <cuda_runtime.h>
#include <cstdint>

#define BS   64
#define NQ   3000
#define NC   256
#define FH   100
#define FW   100
#define TOPK 1500

// Monotone float -> uint key (total order matches float compare for finite vals)
__device__ __forceinline__ unsigned f2key(float f) {
    unsigned u = __float_as_uint(f);
    return u ^ ((u >> 31) ? 0xFFFFFFFFu : 0x80000000u);
}

// ---------------------------------------------------------------------------
// Fused kernel: one block per batch.
//   Phase 1: row-max over NC=256 classes -> smem keys (warp per row, coalesced)
//   Phase 2: 8-bit radix select of top-1500 threshold T + tie count
//   Phase 3: selection flags (index-order ties)
//   Phase 4: selected rects -> 4-corner atomicAdds on 101x101 difference grid
//            (aliased over the dead keys array)
//   Phase 5: vertical + horizontal prefix sums; write output fused w/ padding
// ---------------------------------------------------------------------------
union SMemAlias {
    unsigned keys[NQ];            // phases 1-3
    int      diff[101 * 101];     // phases 4-5 (40804 B)
};

__global__ __launch_bounds__(1024, 1)
void fused_kernel(const float* __restrict__ cls,
                  const float* __restrict__ coord,
                  const int*   __restrict__ vfs,
                  float*       __restrict__ out) {
    const int b    = blockIdx.x;
    const int tid  = threadIdx.x;
    const int lane = tid & 31;
    const int wid  = tid >> 5;

    __shared__ SMemAlias sm;
    __shared__ unsigned s_hist[256];
    __shared__ unsigned s_sel[2];
    __shared__ unsigned s_woff[32];

    // ---- Phase 1: scores. Warp w handles rows w, w+32, ... (94 iters) ----
    {
        const float4* base = reinterpret_cast<const float4*>(
            cls + (size_t)b * NQ * NC);
        for (int row = wid; row < NQ; row += 32) {
            const float4* r = base + (size_t)row * (NC / 4);
            float4 a = __ldcs(&r[lane]);
            float4 c = __ldcs(&r[lane + 32]);
            float m = fmaxf(fmaxf(fmaxf(a.x, a.y), fmaxf(a.z, a.w)),
                            fmaxf(fmaxf(c.x, c.y), fmaxf(c.z, c.w)));
#pragma unroll
            for (int o = 16; o; o >>= 1)
                m = fmaxf(m, __shfl_xor_sync(0xFFFFFFFFu, m, o));
            if (lane == 0) sm.keys[row] = f2key(m);
        }
    }
    __syncthreads();

    // ---- load keys: 3 contiguous queries per thread (index order) ----
    unsigned k[3];
#pragma unroll
    for (int j = 0; j < 3; j++) {
        int q = tid * 3 + j;
        k[j] = (q < NQ) ? sm.keys[q] : 0u;
    }

    // ---- Phase 2: 8-bit radix select: T = max{x : count_ge(x) >= TOPK} ----
    unsigned prefix = 0;
    unsigned need = TOPK;
#pragma unroll
    for (int pass = 0; pass < 4; pass++) {
        const int shift = 24 - 8 * pass;
        if (tid < 256) s_hist[tid] = 0u;
        __syncthreads();
#pragma unroll
        for (int j = 0; j < 3; j++) {
            unsigned kk = k[j];
            bool active = (pass == 0) || ((kk >> (shift + 8)) == prefix);
            if (active) atomicAdd(&s_hist[(kk >> shift) & 255u], 1u);
        }
        __syncthreads();
        if (tid < 32) {
            unsigned loc[8]; unsigned s = 0;
#pragma unroll
            for (int i = 0; i < 8; i++) { loc[i] = s_hist[lane * 8 + i]; s += loc[i]; }
            unsigned v = s;   // suffix sum over lanes >= lane
#pragma unroll
            for (int o = 1; o < 32; o <<= 1) {
                unsigned u = __shfl_down_sync(0xFFFFFFFFu, v, o);
                if (lane + o < 32) v += u;
            }
            unsigned excl = v - s;   // count in strictly higher 8-bin groups
            if (excl < need && excl + s >= need) {
                unsigned cum = excl;
#pragma unroll
                for (int i = 7; i >= 0; i--) {
                    unsigned c2 = cum + loc[i];
                    if (cum < need && c2 >= need) {
                        s_sel[0] = (unsigned)(lane * 8 + i);
                        s_sel[1] = need - cum;    // ties still required
                    }
                    cum = c2;
                }
            }
        }
        __syncthreads();
        prefix = (prefix << 8) | s_sel[0];
        need   = s_sel[1];
        __syncthreads();
    }
    const unsigned T = prefix;
    const unsigned need_eq = need;

    // ---- Phase 3a: tie scan (rank among k==T in index order) ----
    unsigned e = 0;
#pragma unroll
    for (int j = 0; j < 3; j++) e += (k[j] == T);
    unsigned my_off;
    {
        unsigned inc = e;
#pragma unroll
        for (int o = 1; o < 32; o <<= 1) {
            unsigned u = __shfl_up_sync(0xFFFFFFFFu, inc, o);
            if (lane >= o) inc += u;
        }
        if (lane == 31) s_woff[wid] = inc;
        __syncthreads();
        if (tid < 32) {
            unsigned v = s_woff[lane], i2 = v;
#pragma unroll
            for (int o = 1; o < 32; o <<= 1) {
                unsigned u = __shfl_up_sync(0xFFFFFFFFu, i2, o);
                if (lane >= o) i2 += u;
            }
            s_woff[lane] = i2 - v;
        }
        __syncthreads();
        my_off = s_woff[wid] + (inc - e);
    }

    // ---- Phase 3b: selection flags (registers only; keys may die after) ----
    bool selj[3];
    {
        unsigned cum = 0;
#pragma unroll
        for (int j = 0; j < 3; j++) {
            int q = tid * 3 + j;
            bool s = false;
            if (q < NQ) {
                if (k[j] > T) s = true;
                else if (k[j] == T) { s = (my_off + cum < need_eq); cum++; }
            }
            selj[j] = s;
        }
    }

    // ---- Phase 4: zero diff grid (aliases keys), then rect corner atomics ----
    __syncthreads();                       // everyone done reading sm.keys
    for (int i = tid; i < 101 * 101; i += 1024) sm.diff[i] = 0;
    __syncthreads();

    const float fvh = (float)vfs[b * 2 + 0];
    const float fvw = (float)vfs[b * 2 + 1];
#pragma unroll
    for (int j = 0; j < 3; j++) {
        if (selj[j]) {
            int q = tid * 3 + j;
            float4 c4 = *reinterpret_cast<const float4*>(coord + ((size_t)b * NQ + q) * 4);
            // Non-contracted IEEE ops to match XLA bit-for-bit at floor boundaries
            float hw = __fmul_rn(0.5f, c4.z);
            float hh = __fmul_rn(0.5f, c4.w);
            float x0 = __fsub_rn(c4.x, hw);
            float y0 = __fsub_rn(c4.y, hh);
            float x1 = __fadd_rn(c4.x, hw);
            float y1 = __fadd_rn(c4.y, hh);
            int lx = (int)floorf(__fmul_rn(x0, fvh));
            int ly = (int)floorf(__fmul_rn(y0, fvw));
            int rx = (int)floorf(__fmul_rn(x1, fvh));
            int ry = (int)floorf(__fmul_rn(y1, fvw));
            // clamp to [0,100]; monotone so lc<=rc, lyc<=ryc; degenerate
            // rects self-cancel in the difference grid.
            int lc  = min(max(lx, 0), FW);
            int rc  = min(max(rx, 0), FW);
            int lyc = min(max(ly, 0), FH);
            int ryc = min(max(ry, 0), FH);
            atomicAdd(&sm.diff[lyc * 101 + lc],  1);
            atomicAdd(&sm.diff[lyc * 101 + rc], -1);
            atomicAdd(&sm.diff[ryc * 101 + lc], -1);
            atomicAdd(&sm.diff[ryc * 101 + rc],  1);
        }
    }
    __syncthreads();

    // ---- Phase 5a: vertical prefix (thread = column, consecutive addrs) ----
    if (tid < FW) {
        int s = 0;
#pragma unroll 4
        for (int r = 0; r < FH; r++) {
            s += sm.diff[r * 101 + tid];
            sm.diff[r * 101 + tid] = s;
        }
    }
    __syncthreads();

    // ---- Phase 5b: horizontal prefix + fused output write ----
    const int vh = vfs[b * 2 + 0];
    const int vw = vfs[b * 2 + 1];
    if (tid < FH) {
        const int r = tid;
        float* orow = out + (size_t)b * FH * FW + r * FW;
        const bool rowpad = (r >= vh);
        int s = 0;
#pragma unroll 4
        for (int c = 0; c < FW; c++) {
            s += sm.diff[r * 101 + c];
            bool ok = (s > 0) && !rowpad && (c < vw);
            orow[c] = ok ? 0.0f : -1e20f;
        }
    }
}

// ---------------------------------------------------------------------------
extern "C" void kernel_launch(void* const* d_in, const int* in_sizes, int n_in,
                              void* d_out, int out_size) {
    const float* coord = (const float*)d_in[0];  // (BS, NQ, 4) f32
    const float* cls   = (const float*)d_in[1];  // (BS, NQ, NC) f32
    const int*   vfs   = (const int*)d_in[2];    // (BS, 2) i32
    float* out = (float*)d_out;                  // (BS, FH*FW) f32

    fused_kernel<<<BS, 1024>>>(cls, coord, vfs, out);
}

// round 7
// speedup vs baseline: 1.1326x; 1.1326x over previous
#include <cuda_runtime.h>
#include <cstdint>

#define BS   64
#define NQ   3000
#define NC   256
#define FH   100
#define FW   100
#define TOPK 1500

// Scratch: per-(b,q) monotone keys (no cudaMalloc allowed).
__device__ unsigned g_keys[BS * NQ];

// Monotone float -> uint key (total order matches float compare for finite vals)
__device__ __forceinline__ unsigned f2key(float f) {
    unsigned u = __float_as_uint(f);
    return u ^ ((u >> 31) ? 0xFFFFFFFFu : 0x80000000u);
}

// ---------------------------------------------------------------------------
// Kernel 1: keys[b,q] = f2key(max over NC=256 classes). One warp per 4 rows.
// 8 independent LDG.128 per thread (MLP_p1=8) to hide DRAM latency.
// ---------------------------------------------------------------------------
__global__ __launch_bounds__(256) void scores_kernel(const float* __restrict__ cls) {
    int warp = (blockIdx.x * blockDim.x + threadIdx.x) >> 5;
    int lane = threadIdx.x & 31;
    int row0 = warp * 4;
    if (row0 >= BS * NQ) return;

    const float4* r0 = reinterpret_cast<const float4*>(cls + (size_t)(row0 + 0) * NC);
    const float4* r1 = reinterpret_cast<const float4*>(cls + (size_t)(row0 + 1) * NC);
    const float4* r2 = reinterpret_cast<const float4*>(cls + (size_t)(row0 + 2) * NC);
    const float4* r3 = reinterpret_cast<const float4*>(cls + (size_t)(row0 + 3) * NC);

    float4 a0 = __ldcs(&r0[lane]);
    float4 b0 = __ldcs(&r0[lane + 32]);
    float4 a1 = __ldcs(&r1[lane]);
    float4 b1 = __ldcs(&r1[lane + 32]);
    float4 a2 = __ldcs(&r2[lane]);
    float4 b2 = __ldcs(&r2[lane + 32]);
    float4 a3 = __ldcs(&r3[lane]);
    float4 b3 = __ldcs(&r3[lane + 32]);

    float m0 = fmaxf(fmaxf(fmaxf(a0.x, a0.y), fmaxf(a0.z, a0.w)),
                     fmaxf(fmaxf(b0.x, b0.y), fmaxf(b0.z, b0.w)));
    float m1 = fmaxf(fmaxf(fmaxf(a1.x, a1.y), fmaxf(a1.z, a1.w)),
                     fmaxf(fmaxf(b1.x, b1.y), fmaxf(b1.z, b1.w)));
    float m2 = fmaxf(fmaxf(fmaxf(a2.x, a2.y), fmaxf(a2.z, a2.w)),
                     fmaxf(fmaxf(b2.x, b2.y), fmaxf(b2.z, b2.w)));
    float m3 = fmaxf(fmaxf(fmaxf(a3.x, a3.y), fmaxf(a3.z, a3.w)),
                     fmaxf(fmaxf(b3.x, b3.y), fmaxf(b3.z, b3.w)));
#pragma unroll
    for (int o = 16; o; o >>= 1) {
        m0 = fmaxf(m0, __shfl_xor_sync(0xFFFFFFFFu, m0, o));
        m1 = fmaxf(m1, __shfl_xor_sync(0xFFFFFFFFu, m1, o));
        m2 = fmaxf(m2, __shfl_xor_sync(0xFFFFFFFFu, m2, o));
        m3 = fmaxf(m3, __shfl_xor_sync(0xFFFFFFFFu, m3, o));
    }
    if (lane == 0) {
        uint4 kv = make_uint4(f2key(m0), f2key(m1), f2key(m2), f2key(m3));
        *reinterpret_cast<uint4*>(&g_keys[row0]) = kv;
    }
}

// ---------------------------------------------------------------------------
// Kernel 2: per-batch radix top-k threshold + difference-grid mask.
// One block per batch, 1024 threads. Threads 0..749 own 4 keys each (uint4).
// ---------------------------------------------------------------------------
__global__ __launch_bounds__(1024, 1)
void mask_kernel(const float* __restrict__ coord,
                 const int*   __restrict__ vfs,
                 float*       __restrict__ out) {
    const int b    = blockIdx.x;
    const int tid  = threadIdx.x;
    const int lane = tid & 31;
    const int wid  = tid >> 5;

    __shared__ int      s_diff[101 * 101];   // difference grid
    __shared__ int      s_aux[1000];         // segmented-scan offsets
    __shared__ unsigned s_hist[256];
    __shared__ unsigned s_sel[2];
    __shared__ unsigned s_woff[32];

    // ---- zero diff grid (all threads) ----
    for (int i = tid; i < 101 * 101; i += 1024) s_diff[i] = 0;

    // ---- load keys: 4 contiguous queries per thread, vectorized ----
    const bool owner = (tid < NQ / 4);       // 750 threads * 4 = 3000 exactly
    unsigned k[4] = {0u, 0u, 0u, 0u};
    if (owner) {
        uint4 kv = reinterpret_cast<const uint4*>(g_keys + (size_t)b * NQ)[tid];
        k[0] = kv.x; k[1] = kv.y; k[2] = kv.z; k[3] = kv.w;
    }

    // ---- 8-bit radix select: T = max{x : count_ge(x) >= TOPK} ----
    unsigned prefix = 0;
    unsigned need = TOPK;
#pragma unroll
    for (int pass = 0; pass < 4; pass++) {
        const int shift = 24 - 8 * pass;
        if (tid < 256) s_hist[tid] = 0u;
        __syncthreads();
        if (owner) {
#pragma unroll
            for (int j = 0; j < 4; j++) {
                unsigned kk = k[j];
                bool active = (pass == 0) || ((kk >> (shift + 8)) == prefix);
                if (active) atomicAdd(&s_hist[(kk >> shift) & 255u], 1u);
            }
        }
        __syncthreads();
        if (tid < 32) {
            unsigned loc[8]; unsigned s = 0;
#pragma unroll
            for (int i = 0; i < 8; i++) { loc[i] = s_hist[lane * 8 + i]; s += loc[i]; }
            unsigned v = s;   // suffix sum over lanes >= lane
#pragma unroll
            for (int o = 1; o < 32; o <<= 1) {
                unsigned u = __shfl_down_sync(0xFFFFFFFFu, v, o);
                if (lane + o < 32) v += u;
            }
            unsigned excl = v - s;   // count in strictly higher 8-bin groups
            if (excl < need && excl + s >= need) {
                unsigned cum = excl;
#pragma unroll
                for (int i = 7; i >= 0; i--) {
                    unsigned c2 = cum + loc[i];
                    if (cum < need && c2 >= need) {
                        s_sel[0] = (unsigned)(lane * 8 + i);
                        s_sel[1] = need - cum;    // ties still required
                    }
                    cum = c2;
                }
            }
        }
        __syncthreads();
        prefix = (prefix << 8) | s_sel[0];
        need   = s_sel[1];
        __syncthreads();
    }
    const unsigned T = prefix;
    const unsigned need_eq = need;

    // ---- tie scan: rank among k==T in index order ----
    unsigned e = 0;
    if (owner) {
#pragma unroll
        for (int j = 0; j < 4; j++) e += (k[j] == T);
    }
    unsigned my_off;
    {
        unsigned inc = e;
#pragma unroll
        for (int o = 1; o < 32; o <<= 1) {
            unsigned u = __shfl_up_sync(0xFFFFFFFFu, inc, o);
            if (lane >= o) inc += u;
        }
        if (lane == 31) s_woff[wid] = inc;
        __syncthreads();
        if (tid < 32) {
            unsigned v = s_woff[lane], i2 = v;
#pragma unroll
            for (int o = 1; o < 32; o <<= 1) {
                unsigned u = __shfl_up_sync(0xFFFFFFFFu, i2, o);
                if (lane >= o) i2 += u;
            }
            s_woff[lane] = i2 - v;
        }
        __syncthreads();
        my_off = s_woff[wid] + (inc - e);
    }

    // ---- selection flags + rect corner atomics on difference grid ----
    const float fvh = (float)vfs[b * 2 + 0];
    const float fvw = (float)vfs[b * 2 + 1];
    if (owner) {
        unsigned cum = 0;
#pragma unroll
        for (int j = 0; j < 4; j++) {
            bool sel = false;
            if (k[j] > T) sel = true;
            else if (k[j] == T) { sel = (my_off + cum < need_eq); cum++; }
            if (sel) {
                int q = tid * 4 + j;
                float4 c4 = *reinterpret_cast<const float4*>(
                    coord + ((size_t)b * NQ + q) * 4);
                // Non-contracted IEEE ops: match XLA at floor boundaries
                float hw = __fmul_rn(0.5f, c4.z);
                float hh = __fmul_rn(0.5f, c4.w);
                float x0 = __fsub_rn(c4.x, hw);
                float y0 = __fsub_rn(c4.y, hh);
                float x1 = __fadd_rn(c4.x, hw);
                float y1 = __fadd_rn(c4.y, hh);
                int lx = (int)floorf(__fmul_rn(x0, fvh));
                int ly = (int)floorf(__fmul_rn(y0, fvw));
                int rx = (int)floorf(__fmul_rn(x1, fvh));
                int ry = (int)floorf(__fmul_rn(y1, fvw));
                // clamp to [0,100]; monotone so lc<=rc, lyc<=ryc; degenerate
                // rects self-cancel in the difference grid.
                int lc  = min(max(lx, 0), FW);
                int rc  = min(max(rx, 0), FW);
                int lyc = min(max(ly, 0), FH);
                int ryc = min(max(ry, 0), FH);
                atomicAdd(&s_diff[lyc * 101 + lc],  1);
                atomicAdd(&s_diff[lyc * 101 + rc], -1);
                atomicAdd(&s_diff[ryc * 101 + lc], -1);
                atomicAdd(&s_diff[ryc * 101 + rc],  1);
            }
        }
    }
    __syncthreads();

    // ---- vertical prefix over rows, segmented: 10 segments x 100 cols ----
    {
        if (tid < 1000) {
            int col = tid % 100, s = tid / 100;
            int base = (s * 10) * 101 + col;
            int sum = 0;
#pragma unroll
            for (int r = 0; r < 10; r++) {
                sum += s_diff[base + r * 101];
                s_diff[base + r * 101] = sum;     // local inclusive prefix
            }
        }
        __syncthreads();
        if (tid < 100) {                          // exclusive scan of seg totals
            int col = tid, acc = 0;
#pragma unroll
            for (int s = 0; s < 10; s++) {
                s_aux[s * 100 + col] = acc;
                acc += s_diff[(s * 10 + 9) * 101 + col];
            }
        }
        __syncthreads();
        if (tid < 1000) {
            int col = tid % 100, s = tid / 100;
            int off = s_aux[s * 100 + col];
            if (off != 0) {
                int base = (s * 10) * 101 + col;
#pragma unroll
                for (int r = 0; r < 10; r++)
                    s_diff[base + r * 101] += off;
            }
        }
    }
    __syncthreads();

    // ---- horizontal prefix (segmented) fused with output write ----
    const int vh = vfs[b * 2 + 0];
    const int vw = vfs[b * 2 + 1];
    int lc10[10];
    int row = tid / 10, s = tid % 10;
    if (tid < 1000) {
        int base = row * 101 + s * 10;
        int sum = 0;
#pragma unroll
        for (int c = 0; c < 10; c++) {
            sum += s_diff[base + c];
            lc10[c] = sum;                        // local inclusive prefix
        }
        s_aux[tid] = sum;                         // segment total
    }
    __syncthreads();
    if (tid < 100) {                              // exclusive scan per row
        int acc = 0;
#pragma unroll
        for (int j = 0; j < 10; j++) {
            int t = s_aux[tid * 10 + j];
            s_aux[tid * 10 + j] = acc;
            acc += t;
        }
    }
    __syncthreads();
    if (tid < 1000) {
        int off = s_aux[tid];
        const bool rowpad = (row >= vh);
        float* orow = out + (size_t)b * FH * FW + row * FW + s * 10;
#pragma unroll
        for (int c = 0; c < 10; c++) {
            int col = s * 10 + c;
            bool ok = (lc10[c] + off > 0) && !rowpad && (col < vw);
            orow[c] = ok ? 0.0f : -1e20f;
        }
    }
}

// ---------------------------------------------------------------------------
extern "C" void kernel_launch(void* const* d_in, const int* in_sizes, int n_in,
                              void* d_out, int out_size) {
    const float* coord = (const float*)d_in[0];  // (BS, NQ, 4) f32
    const float* cls   = (const float*)d_in[1];  // (BS, NQ, NC) f32
    const int*   vfs   = (const int*)d_in[2];    // (BS, 2) i32
    float* out = (float*)d_out;                  // (BS, FH*FW) f32

    int nwarps = (BS * NQ) / 4;                  // one warp per 4 rows
    int threads = 256;
    int blocks = (nwarps * 32 + threads - 1) / threads;  // 6000
    scores_kernel<<<blocks, threads>>>(cls);
    mask_kernel<<<BS, 1024>>>(coord, vfs, out);
}